// round 12
// baseline (speedup 1.0000x reference)
#include <cuda_runtime.h>
#include <cstdint>

// out[b, 0:128]   = emb[idx[b], :]    (128 f32)
// out[b, 128:146] = genre[idx[b], :]  (18 f32)
// idx is int32 (JAX downcasts int64 without x64).
//
// TWO-PASS INDEX-RANGE PARTITIONING, BRANCHLESS GATHERS:
//   pass 0: rows with idx in [0, 50000); pass 1: [50000, 100000).
//   Live table slice per pass ~29 MB << 126 MB L2 -> gather hits ~100%,
//   removing the ~180 MB/launch of table re-reads (R10 proved the byte cut:
//   651 MB total).
//   R10's per-pass starvation came from DIVERGENT predicated loads
//   (BSSY/BSYNC serialization). Fix: clamp out-of-range indices into the
//   slice (eff = act ? item : lo) and gather UNCONDITIONALLY -> MLP identical
//   to the R5 kernel; only stores are predicated (short @P STG arms).
// Stores: __stcs float2 (evict-first streaming; R5-proven).

#define ROWS_PER_WARP 4
#define SPLIT_ITEM 50000

__global__ void __launch_bounds__(256)
item_gather_concat_kernel(const int*    __restrict__ idx,
                          const float4* __restrict__ emb,   // [N, 32] float4
                          const float2* __restrict__ gen,   // [N, 9]  float2
                          float2*       __restrict__ out,   // [B, 73] float2
                          int B, int loItem, int hiItem)
{
    const int lane  = threadIdx.x & 31;
    const int gwarp = (int)((blockIdx.x * (unsigned)blockDim.x + threadIdx.x) >> 5);
    const int r0    = gwarp * ROWS_PER_WARP;

    if (r0 + ROWS_PER_WARP <= B) {
        int4 iv = __ldcs((const int4*)(idx + r0));   // read-once broadcast
        int items[4] = {iv.x, iv.y, iv.z, iv.w};

        bool act[4];
        int  eff[4];
        #pragma unroll
        for (int j = 0; j < 4; j++) {
            act[j] = (items[j] >= loItem) && (items[j] < hiItem);
            eff[j] = act[j] ? items[j] : loItem;     // clamp into slice (SEL, no branch)
        }

        // Unconditional gathers: full MLP, all reads stay inside the slice.
        float4 e[4];
        float2 g[4];
        #pragma unroll
        for (int j = 0; j < 4; j++)
            e[j] = __ldg(&emb[(size_t)eff[j] * 32 + lane]);
        #pragma unroll
        for (int j = 0; j < 4; j++)
            if (lane < 9)
                g[j] = __ldg(&gen[(size_t)eff[j] * 9 + lane]);

        // Predicated stores (short arms -> @P STG, no divergence).
        #pragma unroll
        for (int j = 0; j < 4; j++) {
            float2* o = out + (size_t)(r0 + j) * 73;   // 8B-aligned rows
            if (act[j]) {
                __stcs(&o[lane * 2 + 0], make_float2(e[j].x, e[j].y));
                __stcs(&o[lane * 2 + 1], make_float2(e[j].z, e[j].w));
            }
            if (act[j] && lane < 9)
                __stcs(&o[64 + lane], g[j]);
        }
    } else {
        // Tail fallback (unused for B = 1M): one row at a time.
        for (int r = r0; r < B && r < r0 + ROWS_PER_WARP; r++) {
            int item = idx[r];
            if (item < loItem || item >= hiItem) continue;
            float4 e = __ldg(&emb[(size_t)item * 32 + lane]);
            float2* o = out + (size_t)r * 73;
            o[lane * 2 + 0] = make_float2(e.x, e.y);
            o[lane * 2 + 1] = make_float2(e.z, e.w);
            if (lane < 9)
                o[64 + lane] = __ldg(&gen[(size_t)item * 9 + lane]);
        }
    }
}

extern "C" void kernel_launch(void* const* d_in, const int* in_sizes, int n_in,
                              void* d_out, int out_size)
{
    const int*    idx = (const int*)   d_in[0];
    const float4* emb = (const float4*)d_in[1];
    const float2* gen = (const float2*)d_in[2];
    float2*       out = (float2*)d_out;

    int B = in_sizes[0];                                   // 1048576
    int rowsPerBlock = 8 * ROWS_PER_WARP;                  // 8 warps/block
    int blocks = (B + rowsPerBlock - 1) / rowsPerBlock;    // 32768

    item_gather_concat_kernel<<<blocks, 256>>>(idx, emb, gen, out, B,
                                               0, SPLIT_ITEM);
    item_gather_concat_kernel<<<blocks, 256>>>(idx, emb, gen, out, B,
                                               SPLIT_ITEM, 0x7FFFFFFF);
}

// round 13
// speedup vs baseline: 1.4102x; 1.4102x over previous
#include <cuda_runtime.h>
#include <cstdint>

// out[b, 0:128]   = emb[idx[b], :]    (128 f32)
// out[b, 128:146] = genre[idx[b], :]  (18 f32)
// idx is int32 (JAX downcasts int64 without x64).
//
// R5 structure (warp = 4 rows, MLP-first gathers, __stcs streaming stores)
// + WARP-LEVEL smem staging so stores are STG.128 instead of STG.64:
//   - warp's 4 output rows = 2336 B contiguous, 16B-aligned (4*584 = 146*16)
//   - stage rows into smem (STS.64, warp-private, only __syncwarp needed --
//     no block barrier, so no coupling to other warps' gather tails)
//   - drain as 146 float4 __stcs (4 full sweeps + 18 tail)
// Store instruction count/warp: 12 STG.64 -> ~5 STG.128.

#define ROWS_PER_WARP 4
#define WARP_STAGE_FLOATS (ROWS_PER_WARP * 146)   // 584 floats = 2336 B

__global__ void __launch_bounds__(256)
item_gather_concat_kernel(const int*    __restrict__ idx,
                          const float4* __restrict__ emb,   // [N, 32] float4
                          const float2* __restrict__ gen,   // [N, 9]  float2
                          float4*       __restrict__ out,   // viewed as float4 stream
                          int B)
{
    __shared__ float s[8 * WARP_STAGE_FLOATS];    // 18.7 KB / block

    const int lane  = threadIdx.x & 31;
    const int w     = threadIdx.x >> 5;
    const int gwarp = (int)((blockIdx.x * (unsigned)blockDim.x + threadIdx.x) >> 5);
    const int r0    = gwarp * ROWS_PER_WARP;

    float* sw = s + w * WARP_STAGE_FLOATS;

    if (r0 + ROWS_PER_WARP <= B) {
        int4 iv = __ldcs((const int4*)(idx + r0));   // read-once broadcast
        int items[4] = {iv.x, iv.y, iv.z, iv.w};

        // Issue all independent gathers first (MLP), then stage.
        float4 e[4];
        float2 g[4];
        #pragma unroll
        for (int j = 0; j < 4; j++)
            e[j] = __ldg(&emb[(size_t)items[j] * 32 + lane]);
        #pragma unroll
        for (int j = 0; j < 4; j++)
            if (lane < 9)
                g[j] = __ldg(&gen[(size_t)items[j] * 9 + lane]);

        #pragma unroll
        for (int j = 0; j < 4; j++) {
            float* srow = sw + j * 146;
            *(float2*)(srow + lane * 4)     = make_float2(e[j].x, e[j].y);
            *(float2*)(srow + lane * 4 + 2) = make_float2(e[j].z, e[j].w);
            if (lane < 9)
                *(float2*)(srow + 128 + lane * 2) = g[j];
        }
        __syncwarp();

        // Drain warp's 2336 B as coalesced STG.128 streaming stores.
        const float4* s4 = (const float4*)sw;
        float4* o4 = out + (size_t)gwarp * (WARP_STAGE_FLOATS / 4);  // 146 chunks
        #pragma unroll
        for (int c = 0; c < 4; c++)
            __stcs(&o4[lane + c * 32], s4[lane + c * 32]);
        if (lane < WARP_STAGE_FLOATS / 4 - 128)       // 18 tail chunks
            __stcs(&o4[lane + 128], s4[lane + 128]);
    } else {
        // Tail fallback (unused for B = 1M): one row at a time.
        for (int r = r0; r < B && r < r0 + ROWS_PER_WARP; r++) {
            int item = idx[r];
            float4 e = __ldg(&emb[(size_t)item * 32 + lane]);
            float2* o = (float2*)((float*)out + (size_t)r * 146);
            o[lane * 2 + 0] = make_float2(e.x, e.y);
            o[lane * 2 + 1] = make_float2(e.z, e.w);
            if (lane < 9)
                o[64 + lane] = __ldg(&gen[(size_t)item * 9 + lane]);
        }
    }
}

extern "C" void kernel_launch(void* const* d_in, const int* in_sizes, int n_in,
                              void* d_out, int out_size)
{
    const int*    idx = (const int*)   d_in[0];
    const float4* emb = (const float4*)d_in[1];
    const float2* gen = (const float2*)d_in[2];
    float4*       out = (float4*)d_out;

    int B = in_sizes[0];                                   // 1048576
    int rowsPerBlock = 8 * ROWS_PER_WARP;                  // 8 warps/block
    int blocks = (B + rowsPerBlock - 1) / rowsPerBlock;    // 32768

    item_gather_concat_kernel<<<blocks, 256>>>(idx, emb, gen, out, B);
}